// round 4
// baseline (speedup 1.0000x reference)
#include <cuda_runtime.h>
#include <cstdint>

#define Nn   20000
#define Ee   320000
#define XDIM 128
#define Hh   256
#define LL   4
#define GG   128
#define CC   10
#define EPSF 1e-5f

// ---------------- scratch (static device allocations) ----------------
__device__ float g_h [Nn * Hh];          // final post-BN features (pool input)
__device__ float g_t [Nn * Hh];          // GEMM output (pre-agg)
__device__ float g_t2[Nn * Hh];          // post-agg (pre-BN)
__device__ unsigned int g_ah[Nn * Hh];   // tf32 hi of GEMM A operand
__device__ unsigned int g_al[Nn * Hh];   // tf32 lo
__device__ unsigned int g_xh[Nn * XDIM];
__device__ unsigned int g_xl[Nn * XDIM];
__device__ unsigned int g_wh[(XDIM + LL * Hh) * Hh];
__device__ unsigned int g_wl[(XDIM + LL * Hh) * Hh];
__device__ float g_dinv[Nn];
__device__ int   g_deg[Nn];
__device__ int   g_rowptr[Nn + 1];
__device__ int   g_cursor[Nn];
__device__ int   g_csrc[Ee];
__device__ float g_cw[Ee];
__device__ float g_colsum[Hh];
__device__ float g_colsq[Hh];
__device__ float g_scale[Hh];
__device__ float g_shift[Hh];
__device__ float g_gsum[GG * Hh];
__device__ int   g_gcnt[GG];
__device__ float g_m1[GG * Hh];
__device__ float g_m2[GG * Hh];

// ---------------- tf32 helpers ----------------
__device__ __forceinline__ void split_tf32(float x, unsigned int& hi, unsigned int& lo) {
    unsigned int h;
    asm("cvt.rna.tf32.f32 %0, %1;" : "=r"(h) : "f"(x));
    float r = x - __uint_as_float(h);
    unsigned int l;
    asm("cvt.rna.tf32.f32 %0, %1;" : "=r"(l) : "f"(r));
    hi = h; lo = l;
}

__device__ __forceinline__ void mma_tf32(float4& d,
    unsigned int a0, unsigned int a1, unsigned int a2, unsigned int a3,
    unsigned int b0, unsigned int b1)
{
    asm volatile(
        "mma.sync.aligned.m16n8k8.row.col.f32.tf32.tf32.f32 "
        "{%0,%1,%2,%3}, {%4,%5,%6,%7}, {%8,%9}, {%0,%1,%2,%3};\n"
        : "+f"(d.x), "+f"(d.y), "+f"(d.z), "+f"(d.w)
        : "r"(a0), "r"(a1), "r"(a2), "r"(a3), "r"(b0), "r"(b1));
}

// ---------------- setup ----------------
__global__ void zero_k() {
    int i = blockIdx.x * blockDim.x + threadIdx.x;
    if (i < Nn)      g_deg[i]  = 0;
    if (i < GG * Hh) g_gsum[i] = 0.f;
    if (i < GG)      g_gcnt[i] = 0;
    if (i < Hh)      { g_colsum[i] = 0.f; g_colsq[i] = 0.f; }
}

// split weights (encW, convW) and x into tf32 hi/lo global buffers
#define W4    ((XDIM + LL * Hh) * Hh / 4)     // 73728
#define ENCW4 (XDIM * Hh / 4)                  // 8192
#define X4    (Nn * XDIM / 4)                  // 640000
__global__ void prep_k(const float* __restrict__ encW, const float* __restrict__ convW,
                       const float* __restrict__ x) {
    int i4 = blockIdx.x * blockDim.x + threadIdx.x;
    if (i4 >= W4 + X4) return;
    float4 v;
    unsigned int* dh;
    unsigned int* dl;
    int o;
    if (i4 < W4) {
        const float* s = (i4 < ENCW4) ? (encW + (size_t)i4 * 4)
                                      : (convW + (size_t)(i4 - ENCW4) * 4);
        v = *(const float4*)s;
        dh = g_wh; dl = g_wl; o = i4 * 4;
    } else {
        int j = i4 - W4;
        v = ((const float4*)x)[j];
        dh = g_xh; dl = g_xl; o = j * 4;
    }
    uint4 h, l;
    split_tf32(v.x, h.x, l.x);
    split_tf32(v.y, h.y, l.y);
    split_tf32(v.z, h.z, l.z);
    split_tf32(v.w, h.w, l.w);
    *(uint4*)(dh + o) = h;
    *(uint4*)(dl + o) = l;
}

__global__ void degree_k(const int* __restrict__ dst, const int* __restrict__ batch) {
    int i = blockIdx.x * blockDim.x + threadIdx.x;
    if (i < Ee) atomicAdd(&g_deg[dst[i]], 1);
    if (i < Nn) atomicAdd(&g_gcnt[batch[i]], 1);
}

// scan (vectorized) + dinv
__global__ void scan_k() {
    __shared__ int wsum[32];
    const int CH = 20;
    int tid = threadIdx.x, lane = tid & 31, wid = tid >> 5;
    int base = tid * CH;
    int dv[CH];
    int s = 0;
    if (base < Nn) {
        const int4* dp = (const int4*)(g_deg + base);
#pragma unroll
        for (int q = 0; q < 5; q++) {
            int4 t = dp[q];
            dv[q * 4 + 0] = t.x; dv[q * 4 + 1] = t.y;
            dv[q * 4 + 2] = t.z; dv[q * 4 + 3] = t.w;
        }
#pragma unroll
        for (int c = 0; c < CH; c++) s += dv[c];
    }
    int inc = s;
#pragma unroll
    for (int o = 1; o < 32; o <<= 1) {
        int t = __shfl_up_sync(0xffffffffu, inc, o);
        if (lane >= o) inc += t;
    }
    if (lane == 31) wsum[wid] = inc;
    __syncthreads();
    if (wid == 0) {
        int v = wsum[lane];
        int iv = v;
#pragma unroll
        for (int o = 1; o < 32; o <<= 1) {
            int t = __shfl_up_sync(0xffffffffu, iv, o);
            if (lane >= o) iv += t;
        }
        wsum[lane] = iv - v;  // exclusive
    }
    __syncthreads();
    int off = wsum[wid] + (inc - s);
    if (base < Nn) {
        int p[CH];
        int run = off;
#pragma unroll
        for (int c = 0; c < CH; c++) { p[c] = run; run += dv[c]; }
        int4*   rp = (int4*)(g_rowptr + base);
        int4*   cp = (int4*)(g_cursor + base);
        float4* fp = (float4*)(g_dinv + base);
#pragma unroll
        for (int q = 0; q < 5; q++) {
            int4 t; t.x = p[q*4]; t.y = p[q*4+1]; t.z = p[q*4+2]; t.w = p[q*4+3];
            rp[q] = t; cp[q] = t;
            float4 f;
            f.x = rsqrtf((float)dv[q*4+0] + 1.f);
            f.y = rsqrtf((float)dv[q*4+1] + 1.f);
            f.z = rsqrtf((float)dv[q*4+2] + 1.f);
            f.w = rsqrtf((float)dv[q*4+3] + 1.f);
            fp[q] = f;
        }
    }
    if (base == Nn) g_rowptr[Nn] = off;
}

__global__ void place_k(const int* __restrict__ src, const int* __restrict__ dst) {
    int i = blockIdx.x * blockDim.x + threadIdx.x;
    if (i >= Ee) return;
    int s = src[i], d = dst[i];
    int pos = atomicAdd(&g_cursor[d], 1);
    g_csrc[pos] = s;
    g_cw[pos]   = g_dinv[s] * g_dinv[d];
}

// ---------------- TF32 tensor-core GEMM (pre-split operands) ----------------
#define BM 128
#define BN 64
#define BK 16
// mode 0: enc  (A = g_xh/g_xl, K=XDIM, +bias, epilogue splits into g_ah/g_al)
// mode 1: conv (A = g_ah/g_al, K=Hh,  epilogue raw -> g_t)
__global__ __launch_bounds__(256) void gemm_k(const float* __restrict__ bias,
                                              int mode, int wofs) {
    __shared__ unsigned int Ah[BK][BM + 8], Al[BK][BM + 8];
    __shared__ unsigned int Bh[BK][BN + 8], Bl[BK][BN + 8];

    const int K = (mode == 0) ? XDIM : Hh;
    const unsigned int* Agh = (mode == 0) ? g_xh : g_ah;
    const unsigned int* Agl = (mode == 0) ? g_xl : g_al;

    const int tid  = threadIdx.x;
    const int lane = tid & 31, wid = tid >> 5;
    const int warp_m = wid & 3;
    const int warp_n = wid >> 2;
    const int rowBase = blockIdx.y * BM;
    const int colBase = blockIdx.x * BN;

    const int arow = tid >> 1;
    const int ak8  = (tid & 1) * 8;
    const int bkr  = tid >> 4;
    const int bnc  = (tid & 15) * 4;

    float4 acc[2][4];
#pragma unroll
    for (int i = 0; i < 2; i++)
#pragma unroll
        for (int j = 0; j < 4; j++) acc[i][j] = make_float4(0.f, 0.f, 0.f, 0.f);

    const int q = lane >> 2;
    const int t = lane & 3;

    for (int k0 = 0; k0 < K; k0 += BK) {
        int gr = rowBase + arow;
        uint4 h0 = make_uint4(0,0,0,0), h1 = h0, l0 = h0, l1 = h0;
        if (gr < Nn) {
            const unsigned int* ap = Agh + (size_t)gr * K + k0 + ak8;
            const unsigned int* al = Agl + (size_t)gr * K + k0 + ak8;
            h0 = *(const uint4*)ap; h1 = *(const uint4*)(ap + 4);
            l0 = *(const uint4*)al; l1 = *(const uint4*)(al + 4);
        }
        Ah[ak8+0][arow]=h0.x; Ah[ak8+1][arow]=h0.y; Ah[ak8+2][arow]=h0.z; Ah[ak8+3][arow]=h0.w;
        Ah[ak8+4][arow]=h1.x; Ah[ak8+5][arow]=h1.y; Ah[ak8+6][arow]=h1.z; Ah[ak8+7][arow]=h1.w;
        Al[ak8+0][arow]=l0.x; Al[ak8+1][arow]=l0.y; Al[ak8+2][arow]=l0.z; Al[ak8+3][arow]=l0.w;
        Al[ak8+4][arow]=l1.x; Al[ak8+5][arow]=l1.y; Al[ak8+6][arow]=l1.z; Al[ak8+7][arow]=l1.w;

        const unsigned int* bp = g_wh + wofs + (size_t)(k0 + bkr) * Hh + colBase + bnc;
        const unsigned int* bl = g_wl + wofs + (size_t)(k0 + bkr) * Hh + colBase + bnc;
        uint4 wh = *(const uint4*)bp;
        uint4 wl = *(const uint4*)bl;
        Bh[bkr][bnc+0]=wh.x; Bh[bkr][bnc+1]=wh.y; Bh[bkr][bnc+2]=wh.z; Bh[bkr][bnc+3]=wh.w;
        Bl[bkr][bnc+0]=wl.x; Bl[bkr][bnc+1]=wl.y; Bl[bkr][bnc+2]=wl.z; Bl[bkr][bnc+3]=wl.w;
        __syncthreads();

#pragma unroll
        for (int ks = 0; ks < 2; ks++) {
            const int kb = ks * 8 + t;
            unsigned int bhf[4][2], blf[4][2];
#pragma unroll
            for (int j = 0; j < 4; j++) {
                int nb = warp_n * 32 + j * 8 + q;
                bhf[j][0] = Bh[kb][nb];     bhf[j][1] = Bh[kb + 4][nb];
                blf[j][0] = Bl[kb][nb];     blf[j][1] = Bl[kb + 4][nb];
            }
#pragma unroll
            for (int i = 0; i < 2; i++) {
                int r0 = warp_m * 32 + i * 16 + q;
                unsigned int ah0 = Ah[kb][r0],     ah1 = Ah[kb][r0 + 8];
                unsigned int ah2 = Ah[kb + 4][r0], ah3 = Ah[kb + 4][r0 + 8];
                unsigned int al0 = Al[kb][r0],     al1 = Al[kb][r0 + 8];
                unsigned int al2 = Al[kb + 4][r0], al3 = Al[kb + 4][r0 + 8];
#pragma unroll
                for (int j = 0; j < 4; j++) {
                    mma_tf32(acc[i][j], ah0, ah1, ah2, ah3, bhf[j][0], bhf[j][1]);
                    mma_tf32(acc[i][j], ah0, ah1, ah2, ah3, blf[j][0], blf[j][1]);
                    mma_tf32(acc[i][j], al0, al1, al2, al3, bhf[j][0], bhf[j][1]);
                }
            }
        }
        __syncthreads();
    }

#pragma unroll
    for (int i = 0; i < 2; i++) {
#pragma unroll
        for (int j = 0; j < 4; j++) {
            int r0 = rowBase + warp_m * 32 + i * 16 + q;
            int c  = colBase + warp_n * 32 + j * 8 + t * 2;
            if (mode == 0) {
                float bx = bias[c], by = bias[c + 1];
                if (r0 < Nn) {
                    unsigned int hh, ll;
                    split_tf32(acc[i][j].x + bx, hh, ll);
                    g_ah[(size_t)r0 * Hh + c] = hh; g_al[(size_t)r0 * Hh + c] = ll;
                    split_tf32(acc[i][j].y + by, hh, ll);
                    g_ah[(size_t)r0 * Hh + c + 1] = hh; g_al[(size_t)r0 * Hh + c + 1] = ll;
                }
                if (r0 + 8 < Nn) {
                    unsigned int hh, ll;
                    split_tf32(acc[i][j].z + bx, hh, ll);
                    g_ah[(size_t)(r0+8) * Hh + c] = hh; g_al[(size_t)(r0+8) * Hh + c] = ll;
                    split_tf32(acc[i][j].w + by, hh, ll);
                    g_ah[(size_t)(r0+8) * Hh + c + 1] = hh; g_al[(size_t)(r0+8) * Hh + c + 1] = ll;
                }
            } else {
                if (r0 < Nn) {
                    g_t[(size_t)r0 * Hh + c]     = acc[i][j].x;
                    g_t[(size_t)r0 * Hh + c + 1] = acc[i][j].y;
                }
                if (r0 + 8 < Nn) {
                    g_t[(size_t)(r0+8) * Hh + c]     = acc[i][j].z;
                    g_t[(size_t)(r0+8) * Hh + c + 1] = acc[i][j].w;
                }
            }
        }
    }
}

// ---------------- aggregate (warp/node CSR gather) + self loop + bias + fused BN stats ----------------
__global__ __launch_bounds__(256) void agg_k(const float* __restrict__ convBi) {
    __shared__ float s_sum[Hh], s_sq[Hh];
    int tid = threadIdx.x, lane = tid & 31;
    s_sum[tid] = 0.f; s_sq[tid] = 0.f;
    __syncthreads();

    int w = blockIdx.x * 8 + (tid >> 5);   // node; grid = 2500 -> exact
    int beg = g_rowptr[w], end = g_rowptr[w + 1];
    float4 a0 = make_float4(0.f, 0.f, 0.f, 0.f), a1 = a0;
    const float4* T = (const float4*)g_t;
    for (int e = beg; e < end; e++) {
        int   s  = g_csrc[e];
        float wt = g_cw[e];
        float4 v0 = T[s * 64 + lane];
        float4 v1 = T[s * 64 + lane + 32];
        a0.x += v0.x * wt; a0.y += v0.y * wt; a0.z += v0.z * wt; a0.w += v0.w * wt;
        a1.x += v1.x * wt; a1.y += v1.y * wt; a1.z += v1.z * wt; a1.w += v1.w * wt;
    }
    float sn = g_dinv[w]; sn *= sn;
    float4 t0 = T[w * 64 + lane], t1 = T[w * 64 + lane + 32];
    const float4* B4 = (const float4*)convBi;
    float4 b0 = B4[lane], b1 = B4[lane + 32];
    a0.x += t0.x * sn + b0.x; a0.y += t0.y * sn + b0.y;
    a0.z += t0.z * sn + b0.z; a0.w += t0.w * sn + b0.w;
    a1.x += t1.x * sn + b1.x; a1.y += t1.y * sn + b1.y;
    a1.z += t1.z * sn + b1.z; a1.w += t1.w * sn + b1.w;
    ((float4*)g_t2)[w * 64 + lane]      = a0;
    ((float4*)g_t2)[w * 64 + lane + 32] = a1;

    int c0 = lane * 4, c1 = 128 + lane * 4;
    atomicAdd(&s_sum[c0+0], a0.x); atomicAdd(&s_sum[c0+1], a0.y);
    atomicAdd(&s_sum[c0+2], a0.z); atomicAdd(&s_sum[c0+3], a0.w);
    atomicAdd(&s_sum[c1+0], a1.x); atomicAdd(&s_sum[c1+1], a1.y);
    atomicAdd(&s_sum[c1+2], a1.z); atomicAdd(&s_sum[c1+3], a1.w);
    atomicAdd(&s_sq[c0+0], a0.x*a0.x); atomicAdd(&s_sq[c0+1], a0.y*a0.y);
    atomicAdd(&s_sq[c0+2], a0.z*a0.z); atomicAdd(&s_sq[c0+3], a0.w*a0.w);
    atomicAdd(&s_sq[c1+0], a1.x*a1.x); atomicAdd(&s_sq[c1+1], a1.y*a1.y);
    atomicAdd(&s_sq[c1+2], a1.z*a1.z); atomicAdd(&s_sq[c1+3], a1.w*a1.w);
    __syncthreads();
    atomicAdd(&g_colsum[tid], s_sum[tid]);
    atomicAdd(&g_colsq[tid],  s_sq[tid]);
}

__global__ void bnprep_k(const float* __restrict__ gamma, const float* __restrict__ beta) {
    int j = threadIdx.x;
    const float invN = 1.f / (float)Nn;
    float m  = g_colsum[j] * invN;
    float v  = g_colsq[j] * invN - m * m;
    float rs = rsqrtf(v + EPSF);
    float sc = gamma[j] * rs;
    g_scale[j] = sc;
    g_shift[j] = beta[j] - m * sc;
    g_colsum[j] = 0.f;   // ready for next layer's agg
    g_colsq[j]  = 0.f;
}

// BN + ReLU + tf32-split: g_t2 -> g_ah/g_al (A operand for next conv GEMM)
__global__ void bnsplit_k() {
    int idx = blockIdx.x * blockDim.x + threadIdx.x;
    if (idx >= Nn * Hh / 4) return;
    int j = (idx & (Hh / 4 - 1)) * 4;
    float4 v = ((const float4*)g_t2)[idx];
    float4 o;
    o.x = fmaxf(v.x * g_scale[j]     + g_shift[j],     0.f);
    o.y = fmaxf(v.y * g_scale[j + 1] + g_shift[j + 1], 0.f);
    o.z = fmaxf(v.z * g_scale[j + 2] + g_shift[j + 2], 0.f);
    o.w = fmaxf(v.w * g_scale[j + 3] + g_shift[j + 3], 0.f);
    uint4 h, l;
    split_tf32(o.x, h.x, l.x);
    split_tf32(o.y, h.y, l.y);
    split_tf32(o.z, h.z, l.z);
    split_tf32(o.w, h.w, l.w);
    ((uint4*)g_ah)[idx] = h;
    ((uint4*)g_al)[idx] = l;
}

// BN + ReLU (final layer, exact fp32) -> g_h for pooling
__global__ void bnrelu_k() {
    int idx = blockIdx.x * blockDim.x + threadIdx.x;
    if (idx >= Nn * Hh / 4) return;
    int j = (idx & (Hh / 4 - 1)) * 4;
    float4 v = ((const float4*)g_t2)[idx];
    float4 o;
    o.x = fmaxf(v.x * g_scale[j]     + g_shift[j],     0.f);
    o.y = fmaxf(v.y * g_scale[j + 1] + g_shift[j + 1], 0.f);
    o.z = fmaxf(v.z * g_scale[j + 2] + g_shift[j + 2], 0.f);
    o.w = fmaxf(v.w * g_scale[j + 3] + g_shift[j + 3], 0.f);
    ((float4*)g_h)[idx] = o;
}

// ---------------- global mean pool (batch sorted) ----------------
__global__ void pool_k(const int* __restrict__ batch) {
    int j  = threadIdx.x;
    int r0 = blockIdx.x * 80;
    int cur = -1;
    float acc = 0.f;
    for (int r = 0; r < 80; r++) {
        int n = r0 + r;
        if (n >= Nn) break;
        int b = batch[n];
        if (b != cur) {
            if (cur >= 0) atomicAdd(&g_gsum[cur * Hh + j], acc);
            cur = b; acc = 0.f;
        }
        acc += g_h[(size_t)n * Hh + j];
    }
    if (cur >= 0) atomicAdd(&g_gsum[cur * Hh + j], acc);
}

// ---------------- MLP head (3 kernels) ----------------
__global__ void mlp1_k(const float* __restrict__ W, const float* __restrict__ b) {
    __shared__ float s[Hh];
    int tid = threadIdx.x;
    int g   = blockIdx.x;
    float inv = 1.f / fmaxf((float)g_gcnt[g], 1.f);
    s[tid] = g_gsum[g * Hh + tid] * inv;
    __syncthreads();
    float sum = b[tid];
#pragma unroll 8
    for (int k = 0; k < Hh; k++) sum += s[k] * W[k * Hh + tid];
    g_m1[g * Hh + tid] = sum;
}

// BN1(+ReLU) fused with second GEMM (stats computed redundantly per block)
__global__ void mlp2_k(const float* __restrict__ gamma, const float* __restrict__ beta,
                       const float* __restrict__ W, const float* __restrict__ b) {
    __shared__ float s[Hh];
    int tid = threadIdx.x;
    int g   = blockIdx.x;
    float su = 0.f, q = 0.f;
    for (int r = 0; r < GG; r++) { float v = g_m1[r * Hh + tid]; su += v; q += v * v; }
    float m   = su * (1.f / GG);
    float var = q * (1.f / GG) - m * m;
    float sc  = gamma[tid] * rsqrtf(var + EPSF);
    float sh  = beta[tid] - m * sc;
    s[tid] = fmaxf(g_m1[g * Hh + tid] * sc + sh, 0.f);
    __syncthreads();
    float sum = b[tid];
#pragma unroll 8
    for (int k = 0; k < Hh; k++) sum += s[k] * W[k * Hh + tid];
    g_m2[g * Hh + tid] = sum;
}

// BN2 fused with final linear
__global__ void final_k(const float* __restrict__ gamma, const float* __restrict__ beta,
                        const float* __restrict__ W3, const float* __restrict__ b3,
                        float* __restrict__ out) {
    __shared__ float s[Hh];
    int tid = threadIdx.x;
    int g   = blockIdx.x;
    float su = 0.f, q = 0.f;
    for (int r = 0; r < GG; r++) { float v = g_m2[r * Hh + tid]; su += v; q += v * v; }
    float m   = su * (1.f / GG);
    float var = q * (1.f / GG) - m * m;
    float sc  = gamma[tid] * rsqrtf(var + EPSF);
    float sh  = beta[tid] - m * sc;
    s[tid] = g_m2[g * Hh + tid] * sc + sh;
    __syncthreads();
    if (tid < CC) {
        float sum = b3[tid];
        for (int k = 0; k < Hh; k++) sum += s[k] * W3[k * CC + tid];
        out[g * CC + tid] = sum;
    }
}

// ---------------- launch ----------------
extern "C" void kernel_launch(void* const* d_in, const int* in_sizes, int n_in,
                              void* d_out, int out_size) {
    const float* x     = (const float*)d_in[0];
    const int*   ei    = (const int*)  d_in[1];
    const int*   batch = (const int*)  d_in[2];
    const float* encW  = (const float*)d_in[3];
    const float* encB  = (const float*)d_in[4];
    const float* convW = (const float*)d_in[5];
    const float* convB = (const float*)d_in[6];
    const float* bnG   = (const float*)d_in[7];
    const float* bnB   = (const float*)d_in[8];
    const float* fcW1  = (const float*)d_in[9];
    const float* fcB1  = (const float*)d_in[10];
    const float* fcG1  = (const float*)d_in[11];
    const float* fcBe1 = (const float*)d_in[12];
    const float* fcW2  = (const float*)d_in[13];
    const float* fcB2  = (const float*)d_in[14];
    const float* fcG2  = (const float*)d_in[15];
    const float* fcBe2 = (const float*)d_in[16];
    const float* fcW3  = (const float*)d_in[17];
    const float* fcB3  = (const float*)d_in[18];
    const int* srcp = ei;
    const int* dstp = ei + Ee;
    float* out = (float*)d_out;

    dim3 gg(Hh / BN, (Nn + BM - 1) / BM);
    int bnBlocks = (Nn * Hh / 4 + 255) / 256;

    // slots 1-3, slot 4 = conv0 GEMM (ncu capture target)
    zero_k<<<(GG * Hh + 255) / 256, 256>>>();
    prep_k<<<(W4 + X4 + 255) / 256, 256>>>(encW, convW, x);
    gemm_k<<<gg, 256>>>(encB, 0, 0);                                // enc -> split h
    gemm_k<<<gg, 256>>>(nullptr, 1, XDIM * Hh);                      // conv0 GEMM  [captured]

    // CSR build (needed before agg)
    degree_k<<<(Ee + 255) / 256, 256>>>(dstp, batch);
    scan_k  <<<1, 1024>>>();
    place_k <<<(Ee + 255) / 256, 256>>>(srcp, dstp);

    for (int l = 0; l < LL; l++) {
        if (l > 0) gemm_k<<<gg, 256>>>(nullptr, 1, (XDIM + l * Hh) * Hh);
        agg_k   <<<Nn / 8, 256>>>(convB + l * Hh);
        bnprep_k<<<1, 256>>>(bnG + l * Hh, bnB + l * Hh);
        if (l < LL - 1) bnsplit_k<<<bnBlocks, 256>>>();
    }
    bnrelu_k<<<bnBlocks, 256>>>();

    pool_k <<<250, 256>>>(batch);
    mlp1_k <<<GG, 256>>>(fcW1, fcB1);
    mlp2_k <<<GG, 256>>>(fcG1, fcBe1, fcW2, fcB2);
    final_k<<<GG, 256>>>(fcG2, fcBe2, fcW3, fcB3, out);
}

// round 5
// speedup vs baseline: 1.1509x; 1.1509x over previous
#include <cuda_runtime.h>
#include <cstdint>

#define Nn   20000
#define Ee   320000
#define XDIM 128
#define Hh   256
#define LL   4
#define GG   128
#define CC   10
#define EPSF 1e-5f

// ---------------- scratch (static device allocations) ----------------
__device__ float g_h [Nn * Hh];          // post-BN features (GEMM A / pool input)
__device__ float g_t [Nn * Hh];          // GEMM output (pre-agg)
__device__ float g_t2[Nn * Hh];          // post-agg (pre-BN)
__device__ unsigned int g_wh[(XDIM + LL * Hh) * Hh];   // tf32 hi of weights
__device__ unsigned int g_wl[(XDIM + LL * Hh) * Hh];   // tf32 lo
__device__ float g_dinv[Nn];
__device__ int   g_deg[Nn];
__device__ int   g_rowptr[Nn + 1];
__device__ int   g_cursor[Nn];
__device__ int   g_csrc[Ee];
__device__ float g_cw[Ee];
__device__ float g_colsum[Hh];
__device__ float g_colsq[Hh];
__device__ float g_scale[Hh];
__device__ float g_shift[Hh];
__device__ float g_gsum[GG * Hh];
__device__ int   g_gcnt[GG];
__device__ float g_m1[GG * Hh];
__device__ float g_m2[GG * Hh];

// ---------------- tf32 helpers ----------------
__device__ __forceinline__ void split_tf32(float x, unsigned int& hi, unsigned int& lo) {
    unsigned int h;
    asm("cvt.rna.tf32.f32 %0, %1;" : "=r"(h) : "f"(x));
    float r = x - __uint_as_float(h);
    unsigned int l;
    asm("cvt.rna.tf32.f32 %0, %1;" : "=r"(l) : "f"(r));
    hi = h; lo = l;
}

__device__ __forceinline__ void mma_tf32(float4& d,
    unsigned int a0, unsigned int a1, unsigned int a2, unsigned int a3,
    unsigned int b0, unsigned int b1)
{
    asm volatile(
        "mma.sync.aligned.m16n8k8.row.col.f32.tf32.tf32.f32 "
        "{%0,%1,%2,%3}, {%4,%5,%6,%7}, {%8,%9}, {%0,%1,%2,%3};\n"
        : "+f"(d.x), "+f"(d.y), "+f"(d.z), "+f"(d.w)
        : "r"(a0), "r"(a1), "r"(a2), "r"(a3), "r"(b0), "r"(b1));
}

// ---------------- setup ----------------
__global__ void zero_k() {
    int i = blockIdx.x * blockDim.x + threadIdx.x;
    if (i < Nn)      g_deg[i]  = 0;
    if (i < GG * Hh) g_gsum[i] = 0.f;
    if (i < GG)      g_gcnt[i] = 0;
    if (i < Hh)      { g_colsum[i] = 0.f; g_colsq[i] = 0.f; }
}

// split weights (encW, convW) into tf32 hi/lo
#define W4    ((XDIM + LL * Hh) * Hh / 4)
#define ENCW4 (XDIM * Hh / 4)
__global__ void prep_k(const float* __restrict__ encW, const float* __restrict__ convW) {
    int i4 = blockIdx.x * blockDim.x + threadIdx.x;
    if (i4 >= W4) return;
    const float* s = (i4 < ENCW4) ? (encW + (size_t)i4 * 4)
                                  : (convW + (size_t)(i4 - ENCW4) * 4);
    float4 v = *(const float4*)s;
    uint4 h, l;
    split_tf32(v.x, h.x, l.x);
    split_tf32(v.y, h.y, l.y);
    split_tf32(v.z, h.z, l.z);
    split_tf32(v.w, h.w, l.w);
    ((uint4*)g_wh)[i4] = h;
    ((uint4*)g_wl)[i4] = l;
}

__global__ void degree_k(const int* __restrict__ dst, const int* __restrict__ batch) {
    int i = blockIdx.x * blockDim.x + threadIdx.x;
    if (i < Ee) atomicAdd(&g_deg[dst[i]], 1);
    if (i < Nn) atomicAdd(&g_gcnt[batch[i]], 1);
}

// scan (vectorized) + dinv
__global__ void scan_k() {
    __shared__ int wsum[32];
    const int CH = 20;
    int tid = threadIdx.x, lane = tid & 31, wid = tid >> 5;
    int base = tid * CH;
    int dv[CH];
    int s = 0;
    if (base < Nn) {
        const int4* dp = (const int4*)(g_deg + base);
#pragma unroll
        for (int q = 0; q < 5; q++) {
            int4 t = dp[q];
            dv[q * 4 + 0] = t.x; dv[q * 4 + 1] = t.y;
            dv[q * 4 + 2] = t.z; dv[q * 4 + 3] = t.w;
        }
#pragma unroll
        for (int c = 0; c < CH; c++) s += dv[c];
    }
    int inc = s;
#pragma unroll
    for (int o = 1; o < 32; o <<= 1) {
        int t = __shfl_up_sync(0xffffffffu, inc, o);
        if (lane >= o) inc += t;
    }
    if (lane == 31) wsum[wid] = inc;
    __syncthreads();
    if (wid == 0) {
        int v = wsum[lane];
        int iv = v;
#pragma unroll
        for (int o = 1; o < 32; o <<= 1) {
            int t = __shfl_up_sync(0xffffffffu, iv, o);
            if (lane >= o) iv += t;
        }
        wsum[lane] = iv - v;
    }
    __syncthreads();
    int off = wsum[wid] + (inc - s);
    if (base < Nn) {
        int p[CH];
        int run = off;
#pragma unroll
        for (int c = 0; c < CH; c++) { p[c] = run; run += dv[c]; }
        int4*   rp = (int4*)(g_rowptr + base);
        int4*   cp = (int4*)(g_cursor + base);
        float4* fp = (float4*)(g_dinv + base);
#pragma unroll
        for (int q = 0; q < 5; q++) {
            int4 t; t.x = p[q*4]; t.y = p[q*4+1]; t.z = p[q*4+2]; t.w = p[q*4+3];
            rp[q] = t; cp[q] = t;
            float4 f;
            f.x = rsqrtf((float)dv[q*4+0] + 1.f);
            f.y = rsqrtf((float)dv[q*4+1] + 1.f);
            f.z = rsqrtf((float)dv[q*4+2] + 1.f);
            f.w = rsqrtf((float)dv[q*4+3] + 1.f);
            fp[q] = f;
        }
    }
    if (base == Nn) g_rowptr[Nn] = off;
}

__global__ void place_k(const int* __restrict__ src, const int* __restrict__ dst) {
    int i = blockIdx.x * blockDim.x + threadIdx.x;
    if (i >= Ee) return;
    int s = src[i], d = dst[i];
    int pos = atomicAdd(&g_cursor[d], 1);
    g_csrc[pos] = s;
    g_cw[pos]   = g_dinv[s] * g_dinv[d];
}

// ---------------- TF32 tensor-core GEMM, double-buffered, XOR-swizzled ----------------
#define BM 128
#define BN 64
#define BK 16
// mode 0: enc  (A = x (param), K=XDIM, +bias, -> g_h)
// mode 1: conv (A = g_h,       K=Hh,          -> g_t)
__global__ __launch_bounds__(256) void gemm_k(const float* __restrict__ xin,
                                              const float* __restrict__ bias,
                                              int mode, int wofs) {
    __shared__ unsigned int Ah[2][BK][BM], Al[2][BK][BM];
    __shared__ unsigned int Bh[2][BK][BN], Bl[2][BK][BN];

    const int K = (mode == 0) ? XDIM : Hh;
    const int KT = K / BK;
    const float* A = (mode == 0) ? xin : g_h;

    const int tid  = threadIdx.x;
    const int lane = tid & 31, wid = tid >> 5;
    const int warp_m = wid & 3;
    const int warp_n = wid >> 2;
    const int rowBase = blockIdx.y * BM;
    const int colBase = blockIdx.x * BN;

    const int arow = tid >> 1;           // 0..127
    const int ak8  = (tid & 1) * 8;      // 0 or 8
    const int bkr  = tid >> 4;           // 0..15
    const int bnc  = (tid & 15) * 4;     // 0..60
    const int bswz = bnc ^ ((bkr & 3) << 3);

    const int q = lane >> 2;             // 0..7
    const int t = lane & 3;              // 0..3
    const int tsw = t << 3;

    const int gr = rowBase + arow;
    const float* aptr = A + (size_t)gr * K + ak8;
    const unsigned int* bhp = g_wh + wofs + (size_t)bkr * Hh + colBase + bnc;
    const unsigned int* blp = g_wl + wofs + (size_t)bkr * Hh + colBase + bnc;

    float4 acc[2][4];
#pragma unroll
    for (int i = 0; i < 2; i++)
#pragma unroll
        for (int j = 0; j < 4; j++) acc[i][j] = make_float4(0.f, 0.f, 0.f, 0.f);

    float va[8];
    uint4 rh, rl;

    // ---- prologue: load tile 0 ----
    {
        float4 v0 = make_float4(0.f,0.f,0.f,0.f), v1 = v0;
        if (gr < Nn) { v0 = *(const float4*)aptr; v1 = *(const float4*)(aptr + 4); }
        va[0]=v0.x; va[1]=v0.y; va[2]=v0.z; va[3]=v0.w;
        va[4]=v1.x; va[5]=v1.y; va[6]=v1.z; va[7]=v1.w;
        rh = *(const uint4*)bhp;
        rl = *(const uint4*)blp;
    }
    // store tile 0 -> buf 0
#pragma unroll
    for (int c = 0; c < 8; c++) {
        unsigned int hh, ll;
        split_tf32(va[c], hh, ll);
        int col = arow ^ ((c & 3) << 3);
        Ah[0][ak8 + c][col] = hh;
        Al[0][ak8 + c][col] = ll;
    }
    *(uint4*)&Bh[0][bkr][bswz] = rh;
    *(uint4*)&Bl[0][bkr][bswz] = rl;
    __syncthreads();

    for (int kt = 0; kt < KT; kt++) {
        const int cur = kt & 1;
        const bool more = (kt + 1 < KT);
        // ---- prefetch next tile (gmem -> regs), overlaps the MMAs below ----
        if (more) {
            float4 v0 = make_float4(0.f,0.f,0.f,0.f), v1 = v0;
            if (gr < Nn) {
                const float* ap = aptr + (kt + 1) * BK;
                v0 = *(const float4*)ap; v1 = *(const float4*)(ap + 4);
            }
            va[0]=v0.x; va[1]=v0.y; va[2]=v0.z; va[3]=v0.w;
            va[4]=v1.x; va[5]=v1.y; va[6]=v1.z; va[7]=v1.w;
            rh = *(const uint4*)(bhp + (size_t)(kt + 1) * BK * Hh);
            rl = *(const uint4*)(blp + (size_t)(kt + 1) * BK * Hh);
        }
        // ---- compute on cur buffer ----
#pragma unroll
        for (int ks = 0; ks < 2; ks++) {
            const int kb = ks * 8 + t;
            unsigned int bhf[4][2], blf[4][2];
#pragma unroll
            for (int j = 0; j < 4; j++) {
                int nb = (warp_n * 32 + j * 8 + q) ^ tsw;
                bhf[j][0] = Bh[cur][kb][nb];     bhf[j][1] = Bh[cur][kb + 4][nb];
                blf[j][0] = Bl[cur][kb][nb];     blf[j][1] = Bl[cur][kb + 4][nb];
            }
#pragma unroll
            for (int i = 0; i < 2; i++) {
                int r0s = (warp_m * 32 + i * 16 + q) ^ tsw;
                int r1s = r0s ^ 8;
                unsigned int ah0 = Ah[cur][kb][r0s],     ah1 = Ah[cur][kb][r1s];
                unsigned int ah2 = Ah[cur][kb + 4][r0s], ah3 = Ah[cur][kb + 4][r1s];
                unsigned int al0 = Al[cur][kb][r0s],     al1 = Al[cur][kb][r1s];
                unsigned int al2 = Al[cur][kb + 4][r0s], al3 = Al[cur][kb + 4][r1s];
#pragma unroll
                for (int j = 0; j < 4; j++) {
                    mma_tf32(acc[i][j], ah0, ah1, ah2, ah3, bhf[j][0], bhf[j][1]);
                    mma_tf32(acc[i][j], ah0, ah1, ah2, ah3, blf[j][0], blf[j][1]);
                    mma_tf32(acc[i][j], al0, al1, al2, al3, bhf[j][0], bhf[j][1]);
                }
            }
        }
        // ---- store prefetched tile into next buffer ----
        if (more) {
            const int nxt = cur ^ 1;
#pragma unroll
            for (int c = 0; c < 8; c++) {
                unsigned int hh, ll;
                split_tf32(va[c], hh, ll);
                int col = arow ^ ((c & 3) << 3);
                Ah[nxt][ak8 + c][col] = hh;
                Al[nxt][ak8 + c][col] = ll;
            }
            *(uint4*)&Bh[nxt][bkr][bswz] = rh;
            *(uint4*)&Bl[nxt][bkr][bswz] = rl;
        }
        __syncthreads();
    }

    // ---- epilogue ----
    float* OUT = (mode == 0) ? g_h : g_t;
#pragma unroll
    for (int i = 0; i < 2; i++) {
#pragma unroll
        for (int j = 0; j < 4; j++) {
            int r0 = rowBase + warp_m * 32 + i * 16 + q;
            int c  = colBase + warp_n * 32 + j * 8 + t * 2;
            float bx = 0.f, by = 0.f;
            if (mode == 0) { bx = bias[c]; by = bias[c + 1]; }
            if (r0 < Nn) {
                OUT[(size_t)r0 * Hh + c]     = acc[i][j].x + bx;
                OUT[(size_t)r0 * Hh + c + 1] = acc[i][j].y + by;
            }
            if (r0 + 8 < Nn) {
                OUT[(size_t)(r0 + 8) * Hh + c]     = acc[i][j].z + bx;
                OUT[(size_t)(r0 + 8) * Hh + c + 1] = acc[i][j].w + by;
            }
        }
    }
}

// ---------------- aggregate (warp/node CSR gather) + self loop + bias + fused BN stats ----------------
__global__ __launch_bounds__(256) void agg_k(const float* __restrict__ convBi) {
    __shared__ float s_sum[Hh], s_sq[Hh];
    int tid = threadIdx.x, lane = tid & 31;
    s_sum[tid] = 0.f; s_sq[tid] = 0.f;
    __syncthreads();

    int w = blockIdx.x * 8 + (tid >> 5);   // grid = 2500 -> exact
    int beg = g_rowptr[w], end = g_rowptr[w + 1];
    float4 a0 = make_float4(0.f, 0.f, 0.f, 0.f), a1 = a0;
    const float4* T = (const float4*)g_t;
    for (int e = beg; e < end; e++) {
        int   s  = g_csrc[e];
        float wt = g_cw[e];
        float4 v0 = T[s * 64 + lane];
        float4 v1 = T[s * 64 + lane + 32];
        a0.x += v0.x * wt; a0.y += v0.y * wt; a0.z += v0.z * wt; a0.w += v0.w * wt;
        a1.x += v1.x * wt; a1.y += v1.y * wt; a1.z += v1.z * wt; a1.w += v1.w * wt;
    }
    float sn = g_dinv[w]; sn *= sn;
    float4 t0 = T[w * 64 + lane], t1 = T[w * 64 + lane + 32];
    const float4* B4 = (const float4*)convBi;
    float4 b0 = B4[lane], b1 = B4[lane + 32];
    a0.x += t0.x * sn + b0.x; a0.y += t0.y * sn + b0.y;
    a0.z += t0.z * sn + b0.z; a0.w += t0.w * sn + b0.w;
    a1.x += t1.x * sn + b1.x; a1.y += t1.y * sn + b1.y;
    a1.z += t1.z * sn + b1.z; a1.w += t1.w * sn + b1.w;
    ((float4*)g_t2)[w * 64 + lane]      = a0;
    ((float4*)g_t2)[w * 64 + lane + 32] = a1;

    int c0 = lane * 4, c1 = 128 + lane * 4;
    atomicAdd(&s_sum[c0+0], a0.x); atomicAdd(&s_sum[c0+1], a0.y);
    atomicAdd(&s_sum[c0+2], a0.z); atomicAdd(&s_sum[c0+3], a0.w);
    atomicAdd(&s_sum[c1+0], a1.x); atomicAdd(&s_sum[c1+1], a1.y);
    atomicAdd(&s_sum[c1+2], a1.z); atomicAdd(&s_sum[c1+3], a1.w);
    atomicAdd(&s_sq[c0+0], a0.x*a0.x); atomicAdd(&s_sq[c0+1], a0.y*a0.y);
    atomicAdd(&s_sq[c0+2], a0.z*a0.z); atomicAdd(&s_sq[c0+3], a0.w*a0.w);
    atomicAdd(&s_sq[c1+0], a1.x*a1.x); atomicAdd(&s_sq[c1+1], a1.y*a1.y);
    atomicAdd(&s_sq[c1+2], a1.z*a1.z); atomicAdd(&s_sq[c1+3], a1.w*a1.w);
    __syncthreads();
    atomicAdd(&g_colsum[tid], s_sum[tid]);
    atomicAdd(&g_colsq[tid],  s_sq[tid]);
}

__global__ void bnprep_k(const float* __restrict__ gamma, const float* __restrict__ beta) {
    int j = threadIdx.x;
    const float invN = 1.f / (float)Nn;
    float m  = g_colsum[j] * invN;
    float v  = g_colsq[j] * invN - m * m;
    float rs = rsqrtf(v + EPSF);
    float sc = gamma[j] * rs;
    g_scale[j] = sc;
    g_shift[j] = beta[j] - m * sc;
    g_colsum[j] = 0.f;
    g_colsq[j]  = 0.f;
}

// BN + ReLU: g_t2 -> g_h
__global__ void bnrelu_k() {
    int idx = blockIdx.x * blockDim.x + threadIdx.x;
    if (idx >= Nn * Hh / 4) return;
    int j = (idx & (Hh / 4 - 1)) * 4;
    float4 v = ((const float4*)g_t2)[idx];
    float4 o;
    o.x = fmaxf(v.x * g_scale[j]     + g_shift[j],     0.f);
    o.y = fmaxf(v.y * g_scale[j + 1] + g_shift[j + 1], 0.f);
    o.z = fmaxf(v.z * g_scale[j + 2] + g_shift[j + 2], 0.f);
    o.w = fmaxf(v.w * g_scale[j + 3] + g_shift[j + 3], 0.f);
    ((float4*)g_h)[idx] = o;
}

// ---------------- global mean pool (batch sorted) ----------------
__global__ void pool_k(const int* __restrict__ batch) {
    int j  = threadIdx.x;
    int r0 = blockIdx.x * 80;
    int cur = -1;
    float acc = 0.f;
    for (int r = 0; r < 80; r++) {
        int n = r0 + r;
        if (n >= Nn) break;
        int b = batch[n];
        if (b != cur) {
            if (cur >= 0) atomicAdd(&g_gsum[cur * Hh + j], acc);
            cur = b; acc = 0.f;
        }
        acc += g_h[(size_t)n * Hh + j];
    }
    if (cur >= 0) atomicAdd(&g_gsum[cur * Hh + j], acc);
}

// ---------------- MLP head ----------------
__global__ void mlp1_k(const float* __restrict__ W, const float* __restrict__ b) {
    __shared__ float s[Hh];
    int tid = threadIdx.x;
    int g   = blockIdx.x;
    float inv = 1.f / fmaxf((float)g_gcnt[g], 1.f);
    s[tid] = g_gsum[g * Hh + tid] * inv;
    __syncthreads();
    float sum = b[tid];
#pragma unroll 8
    for (int k = 0; k < Hh; k++) sum += s[k] * W[k * Hh + tid];
    g_m1[g * Hh + tid] = sum;
}

__global__ void mlp2_k(const float* __restrict__ gamma, const float* __restrict__ beta,
                       const float* __restrict__ W, const float* __restrict__ b) {
    __shared__ float s[Hh];
    int tid = threadIdx.x;
    int g   = blockIdx.x;
    float su = 0.f, q = 0.f;
    for (int r = 0; r < GG; r++) { float v = g_m1[r * Hh + tid]; su += v; q += v * v; }
    float m   = su * (1.f / GG);
    float var = q * (1.f / GG) - m * m;
    float sc  = gamma[tid] * rsqrtf(var + EPSF);
    float sh  = beta[tid] - m * sc;
    s[tid] = fmaxf(g_m1[g * Hh + tid] * sc + sh, 0.f);
    __syncthreads();
    float sum = b[tid];
#pragma unroll 8
    for (int k = 0; k < Hh; k++) sum += s[k] * W[k * Hh + tid];
    g_m2[g * Hh + tid] = sum;
}

__global__ void final_k(const float* __restrict__ gamma, const float* __restrict__ beta,
                        const float* __restrict__ W3, const float* __restrict__ b3,
                        float* __restrict__ out) {
    __shared__ float s[Hh];
    int tid = threadIdx.x;
    int g   = blockIdx.x;
    float su = 0.f, q = 0.f;
    for (int r = 0; r < GG; r++) { float v = g_m2[r * Hh + tid]; su += v; q += v * v; }
    float m   = su * (1.f / GG);
    float var = q * (1.f / GG) - m * m;
    float sc  = gamma[tid] * rsqrtf(var + EPSF);
    float sh  = beta[tid] - m * sc;
    s[tid] = g_m2[g * Hh + tid] * sc + sh;
    __syncthreads();
    if (tid < CC) {
        float sum = b3[tid];
        for (int k = 0; k < Hh; k++) sum += s[k] * W3[k * CC + tid];
        out[g * CC + tid] = sum;
    }
}

// ---------------- launch ----------------
extern "C" void kernel_launch(void* const* d_in, const int* in_sizes, int n_in,
                              void* d_out, int out_size) {
    const float* x     = (const float*)d_in[0];
    const int*   ei    = (const int*)  d_in[1];
    const int*   batch = (const int*)  d_in[2];
    const float* encW  = (const float*)d_in[3];
    const float* encB  = (const float*)d_in[4];
    const float* convW = (const float*)d_in[5];
    const float* convB = (const float*)d_in[6];
    const float* bnG   = (const float*)d_in[7];
    const float* bnB   = (const float*)d_in[8];
    const float* fcW1  = (const float*)d_in[9];
    const float* fcB1  = (const float*)d_in[10];
    const float* fcG1  = (const float*)d_in[11];
    const float* fcBe1 = (const float*)d_in[12];
    const float* fcW2  = (const float*)d_in[13];
    const float* fcB2  = (const float*)d_in[14];
    const float* fcG2  = (const float*)d_in[15];
    const float* fcBe2 = (const float*)d_in[16];
    const float* fcW3  = (const float*)d_in[17];
    const float* fcB3  = (const float*)d_in[18];
    const int* srcp = ei;
    const int* dstp = ei + Ee;
    float* out = (float*)d_out;

    dim3 gg(Hh / BN, (Nn + BM - 1) / BM);
    int bnBlocks = (Nn * Hh / 4 + 255) / 256;

    // slots 1-3, slot 4 = conv0 GEMM (ncu capture target)
    zero_k<<<(GG * Hh + 255) / 256, 256>>>();
    prep_k<<<(W4 + 255) / 256, 256>>>(encW, convW);
    gemm_k<<<gg, 256>>>(x, encB, 0, 0);                       // enc -> g_h
    gemm_k<<<gg, 256>>>(nullptr, nullptr, 1, XDIM * Hh);      // conv0 GEMM [captured]

    // CSR build
    degree_k<<<(Ee + 255) / 256, 256>>>(dstp, batch);
    scan_k  <<<1, 1024>>>();
    place_k <<<(Ee + 255) / 256, 256>>>(srcp, dstp);

    for (int l = 0; l < LL; l++) {
        if (l > 0) gemm_k<<<gg, 256>>>(nullptr, nullptr, 1, (XDIM + l * Hh) * Hh);
        agg_k   <<<Nn / 8, 256>>>(convB + l * Hh);
        bnprep_k<<<1, 256>>>(bnG + l * Hh, bnB + l * Hh);
        bnrelu_k<<<bnBlocks, 256>>>();
    }

    pool_k <<<250, 256>>>(batch);
    mlp1_k <<<GG, 256>>>(fcW1, fcB1);
    mlp2_k <<<GG, 256>>>(fcG1, fcBe1, fcW2, fcB2);
    final_k<<<GG, 256>>>(fcG2, fcBe2, fcW3, fcB3, out);
}

// round 6
// speedup vs baseline: 1.3105x; 1.1386x over previous
#include <cuda_runtime.h>
#include <cuda_fp16.h>
#include <cstdint>

#define Nn   20000
#define Ee   320000
#define XDIM 128
#define Hh   256
#define LL   4
#define GG   128
#define CC   10
#define EPSF 1e-5f

#define KP2TOT ((XDIM + LL * Hh) / 2)   // 576 packed k-pair rows

// ---------------- scratch (static device allocations) ----------------
__device__ float g_h [Nn * Hh];          // enc output / final pool input
__device__ float g_t [Nn * Hh];          // GEMM output (pre-agg)
__device__ float g_t2[Nn * Hh];          // post-agg (pre-BN)
__device__ unsigned int g_wbh[KP2TOT * Hh];  // fp16-hi weights, packed k-pairs
__device__ unsigned int g_wbl[KP2TOT * Hh];  // fp16-lo residual
__device__ float g_dinv[Nn];
__device__ int   g_deg[Nn];
__device__ int   g_rowptr[Nn + 1];
__device__ int   g_cursor[Nn];
__device__ int   g_csrc[Ee];
__device__ float g_cw[Ee];
__device__ float g_colsum[Hh];
__device__ float g_colsq[Hh];
__device__ float g_scale[Hh];
__device__ float g_shift[Hh];
__device__ float g_gsum[GG * Hh];
__device__ int   g_gcnt[GG];
__device__ float g_m1[GG * Hh];
__device__ float g_m2[GG * Hh];

// ---------------- fp16 split helpers ----------------
__device__ __forceinline__ void split_h2(float a, float b,
                                         unsigned int& hi, unsigned int& lo) {
    __half ha = __float2half_rn(a), hb = __float2half_rn(b);
    float ra = a - __half2float(ha);
    float rb = b - __half2float(hb);
    __half2 h = __halves2half2(ha, hb);
    __half2 l = __halves2half2(__float2half_rn(ra), __float2half_rn(rb));
    hi = *reinterpret_cast<unsigned int*>(&h);
    lo = *reinterpret_cast<unsigned int*>(&l);
}

__device__ __forceinline__ void mma_f16(float4& d,
    unsigned int a0, unsigned int a1, unsigned int a2, unsigned int a3,
    unsigned int b0, unsigned int b1)
{
    asm volatile(
        "mma.sync.aligned.m16n8k16.row.col.f32.f16.f16.f32 "
        "{%0,%1,%2,%3}, {%4,%5,%6,%7}, {%8,%9}, {%0,%1,%2,%3};\n"
        : "+f"(d.x), "+f"(d.y), "+f"(d.z), "+f"(d.w)
        : "r"(a0), "r"(a1), "r"(a2), "r"(a3), "r"(b0), "r"(b1));
}

// ---------------- setup ----------------
__global__ void zero_k() {
    int i = blockIdx.x * blockDim.x + threadIdx.x;
    if (i < Nn)      g_deg[i]  = 0;
    if (i < GG * Hh) g_gsum[i] = 0.f;
    if (i < GG)      g_gcnt[i] = 0;
    if (i < Hh)      { g_colsum[i] = 0.f; g_colsq[i] = 0.f; }
}

// pre-split + pre-pack all weights into fp16 hi/lo, k-pair packed layout [kp][256]
__global__ void prep_k(const float* __restrict__ encW, const float* __restrict__ convW) {
    int i = blockIdx.x * blockDim.x + threadIdx.x;
    if (i >= KP2TOT * Hh) return;
    int kp = i >> 8;
    int n  = i & 255;
    int r0 = kp * 2, r1 = r0 + 1;
    float a = (r0 < XDIM) ? encW[r0 * Hh + n] : convW[(size_t)(r0 - XDIM) * Hh + n];
    float b = (r1 < XDIM) ? encW[r1 * Hh + n] : convW[(size_t)(r1 - XDIM) * Hh + n];
    unsigned int hi, lo;
    split_h2(a, b, hi, lo);
    g_wbh[i] = hi;
    g_wbl[i] = lo;
}

__global__ void degree_k(const int* __restrict__ dst, const int* __restrict__ batch) {
    int i = blockIdx.x * blockDim.x + threadIdx.x;
    if (i < Ee) atomicAdd(&g_deg[dst[i]], 1);
    if (i < Nn) atomicAdd(&g_gcnt[batch[i]], 1);
}

// scan (vectorized) + dinv
__global__ void scan_k() {
    __shared__ int wsum[32];
    const int CH = 20;
    int tid = threadIdx.x, lane = tid & 31, wid = tid >> 5;
    int base = tid * CH;
    int dv[CH];
    int s = 0;
    if (base < Nn) {
        const int4* dp = (const int4*)(g_deg + base);
#pragma unroll
        for (int q = 0; q < 5; q++) {
            int4 t = dp[q];
            dv[q * 4 + 0] = t.x; dv[q * 4 + 1] = t.y;
            dv[q * 4 + 2] = t.z; dv[q * 4 + 3] = t.w;
        }
#pragma unroll
        for (int c = 0; c < CH; c++) s += dv[c];
    }
    int inc = s;
#pragma unroll
    for (int o = 1; o < 32; o <<= 1) {
        int t = __shfl_up_sync(0xffffffffu, inc, o);
        if (lane >= o) inc += t;
    }
    if (lane == 31) wsum[wid] = inc;
    __syncthreads();
    if (wid == 0) {
        int v = wsum[lane];
        int iv = v;
#pragma unroll
        for (int o = 1; o < 32; o <<= 1) {
            int t = __shfl_up_sync(0xffffffffu, iv, o);
            if (lane >= o) iv += t;
        }
        wsum[lane] = iv - v;
    }
    __syncthreads();
    int off = wsum[wid] + (inc - s);
    if (base < Nn) {
        int p[CH];
        int run = off;
#pragma unroll
        for (int c = 0; c < CH; c++) { p[c] = run; run += dv[c]; }
        int4*   rp = (int4*)(g_rowptr + base);
        int4*   cp = (int4*)(g_cursor + base);
        float4* fp = (float4*)(g_dinv + base);
#pragma unroll
        for (int q = 0; q < 5; q++) {
            int4 t; t.x = p[q*4]; t.y = p[q*4+1]; t.z = p[q*4+2]; t.w = p[q*4+3];
            rp[q] = t; cp[q] = t;
            float4 f;
            f.x = rsqrtf((float)dv[q*4+0] + 1.f);
            f.y = rsqrtf((float)dv[q*4+1] + 1.f);
            f.z = rsqrtf((float)dv[q*4+2] + 1.f);
            f.w = rsqrtf((float)dv[q*4+3] + 1.f);
            fp[q] = f;
        }
    }
    if (base == Nn) g_rowptr[Nn] = off;
}

__global__ void place_k(const int* __restrict__ src, const int* __restrict__ dst) {
    int i = blockIdx.x * blockDim.x + threadIdx.x;
    if (i >= Ee) return;
    int s = src[i], d = dst[i];
    int pos = atomicAdd(&g_cursor[d], 1);
    g_csrc[pos] = s;
    g_cw[pos]   = g_dinv[s] * g_dinv[d];
}

// ---------------- split-FP16 tensor-core GEMM, double-buffered, swizzled ----------------
#define BM 128
#define BN 64
#define BK 16
// mode 0: enc  (A=x,   +bias,              -> g_h)
// mode 1: conv (A=g_h, raw,                -> g_t)
// mode 2: conv (A=relu(g_t2*scale+shift),  -> g_t)
__global__ __launch_bounds__(256) void gemm_k(const float* __restrict__ xin,
                                              const float* __restrict__ bias,
                                              int mode, int wofs2) {
    __shared__ unsigned int Ah[2][8][BM], Al[2][8][BM];
    __shared__ unsigned int Bh[2][8][BN], Bl[2][8][BN];

    const int K  = (mode == 0) ? XDIM : Hh;
    const int KT = K / BK;
    const float* A = (mode == 0) ? xin : (mode == 1 ? g_h : g_t2);

    const int tid  = threadIdx.x;
    const int lane = tid & 31, wid = tid >> 5;
    const int warp_m = wid & 3, warp_n = wid >> 2;
    const int rowBase = blockIdx.y * BM, colBase = blockIdx.x * BN;

    const int arow = tid >> 1;            // 0..127
    const int ak8  = (tid & 1) * 8;       // 0 or 8 (k offset within tile)
    const int akp  = (tid & 1) * 4;       // kpair plane base (0 or 4)
    const int bkp  = tid >> 5;            // 0..7 kpair plane
    const int bcol = lane * 2;            // 0..62
    const int q = lane >> 2, t = lane & 3, tsw = t << 3;

    const int gr = rowBase + arow;
    const float* aptr = A + (size_t)gr * K + ak8;
    const unsigned int* bhp = g_wbh + wofs2 + (size_t)bkp * Hh + colBase + bcol;
    const unsigned int* blp = g_wbl + wofs2 + (size_t)bkp * Hh + colBase + bcol;
    const int bstep = 8 * Hh;
    const int bcs = bcol ^ ((bkp & 3) << 3);

    float4 acc[2][4];
#pragma unroll
    for (int i = 0; i < 2; i++)
#pragma unroll
        for (int j = 0; j < 4; j++) acc[i][j] = make_float4(0.f, 0.f, 0.f, 0.f);

    float va[8];
    uint2 rbh, rbl;

    // ---- prologue: fetch tile 0 ----
    {
        float4 v0 = make_float4(0.f,0.f,0.f,0.f), v1 = v0;
        if (gr < Nn) { v0 = *(const float4*)aptr; v1 = *(const float4*)(aptr + 4); }
        va[0]=v0.x; va[1]=v0.y; va[2]=v0.z; va[3]=v0.w;
        va[4]=v1.x; va[5]=v1.y; va[6]=v1.z; va[7]=v1.w;
        if (mode == 2) {
            int kk = ak8;
#pragma unroll
            for (int c = 0; c < 8; c++)
                va[c] = fmaxf(va[c] * g_scale[kk + c] + g_shift[kk + c], 0.f);
        }
        rbh = *(const uint2*)bhp;
        rbl = *(const uint2*)blp;
    }
#pragma unroll
    for (int c2 = 0; c2 < 4; c2++) {
        unsigned int hi, lo;
        split_h2(va[2*c2], va[2*c2+1], hi, lo);
        int col = arow ^ (c2 << 3);
        Ah[0][akp + c2][col] = hi;
        Al[0][akp + c2][col] = lo;
    }
    *(uint2*)&Bh[0][bkp][bcs] = rbh;
    *(uint2*)&Bl[0][bkp][bcs] = rbl;
    __syncthreads();

    for (int kt = 0; kt < KT; kt++) {
        const int cur = kt & 1;
        const bool more = (kt + 1 < KT);
        // ---- prefetch next tile (overlaps MMAs) ----
        if (more) {
            float4 v0 = make_float4(0.f,0.f,0.f,0.f), v1 = v0;
            if (gr < Nn) {
                const float* ap = aptr + (kt + 1) * BK;
                v0 = *(const float4*)ap; v1 = *(const float4*)(ap + 4);
            }
            va[0]=v0.x; va[1]=v0.y; va[2]=v0.z; va[3]=v0.w;
            va[4]=v1.x; va[5]=v1.y; va[6]=v1.z; va[7]=v1.w;
            if (mode == 2) {
                int kk = (kt + 1) * BK + ak8;
#pragma unroll
                for (int c = 0; c < 8; c++)
                    va[c] = fmaxf(va[c] * g_scale[kk + c] + g_shift[kk + c], 0.f);
            }
            rbh = *(const uint2*)(bhp + (size_t)(kt + 1) * bstep);
            rbl = *(const uint2*)(blp + (size_t)(kt + 1) * bstep);
        }
        // ---- compute on cur buffer ----
        unsigned int bh0[4], bh1[4], bl0[4], bl1[4];
#pragma unroll
        for (int j = 0; j < 4; j++) {
            int nb = (warp_n * 32 + j * 8 + q) ^ tsw;
            bh0[j] = Bh[cur][t][nb];     bh1[j] = Bh[cur][t + 4][nb];
            bl0[j] = Bl[cur][t][nb];     bl1[j] = Bl[cur][t + 4][nb];
        }
#pragma unroll
        for (int i = 0; i < 2; i++) {
            int r  = warp_m * 32 + i * 16 + q;
            int rs  = r ^ tsw;
            int rs8 = (r + 8) ^ tsw;
            unsigned int ah0 = Ah[cur][t][rs],     ah1 = Ah[cur][t][rs8];
            unsigned int ah2 = Ah[cur][t + 4][rs], ah3 = Ah[cur][t + 4][rs8];
            unsigned int al0 = Al[cur][t][rs],     al1 = Al[cur][t][rs8];
            unsigned int al2 = Al[cur][t + 4][rs], al3 = Al[cur][t + 4][rs8];
#pragma unroll
            for (int j = 0; j < 4; j++) {
                mma_f16(acc[i][j], ah0, ah1, ah2, ah3, bh0[j], bh1[j]);
                mma_f16(acc[i][j], ah0, ah1, ah2, ah3, bl0[j], bl1[j]);
                mma_f16(acc[i][j], al0, al1, al2, al3, bh0[j], bh1[j]);
            }
        }
        // ---- store prefetched tile into next buffer ----
        if (more) {
            const int nxt = cur ^ 1;
#pragma unroll
            for (int c2 = 0; c2 < 4; c2++) {
                unsigned int hi, lo;
                split_h2(va[2*c2], va[2*c2+1], hi, lo);
                int col = arow ^ (c2 << 3);
                Ah[nxt][akp + c2][col] = hi;
                Al[nxt][akp + c2][col] = lo;
            }
            *(uint2*)&Bh[nxt][bkp][bcs] = rbh;
            *(uint2*)&Bl[nxt][bkp][bcs] = rbl;
        }
        __syncthreads();
    }

    // ---- epilogue ----
    float* OUT = (mode == 0) ? g_h : g_t;
#pragma unroll
    for (int i = 0; i < 2; i++) {
#pragma unroll
        for (int j = 0; j < 4; j++) {
            int r0 = rowBase + warp_m * 32 + i * 16 + q;
            int c  = colBase + warp_n * 32 + j * 8 + t * 2;
            float bx = 0.f, by = 0.f;
            if (mode == 0) { bx = bias[c]; by = bias[c + 1]; }
            if (r0 < Nn) {
                OUT[(size_t)r0 * Hh + c]     = acc[i][j].x + bx;
                OUT[(size_t)r0 * Hh + c + 1] = acc[i][j].y + by;
            }
            if (r0 + 8 < Nn) {
                OUT[(size_t)(r0 + 8) * Hh + c]     = acc[i][j].z + bx;
                OUT[(size_t)(r0 + 8) * Hh + c + 1] = acc[i][j].w + by;
            }
        }
    }
}

// ---------------- aggregate (warp/node CSR gather) + self loop + bias + fused BN stats ----------------
__global__ __launch_bounds__(256) void agg_k(const float* __restrict__ convBi) {
    __shared__ float s_sum[Hh], s_sq[Hh];
    int tid = threadIdx.x, lane = tid & 31;
    s_sum[tid] = 0.f; s_sq[tid] = 0.f;
    __syncthreads();

    int w = blockIdx.x * 8 + (tid >> 5);   // grid = 2500 -> exact
    int beg = g_rowptr[w], end = g_rowptr[w + 1];
    float4 a0 = make_float4(0.f, 0.f, 0.f, 0.f), a1 = a0;
    const float4* T = (const float4*)g_t;
    for (int e = beg; e < end; e++) {
        int   s  = g_csrc[e];
        float wt = g_cw[e];
        float4 v0 = T[s * 64 + lane];
        float4 v1 = T[s * 64 + lane + 32];
        a0.x += v0.x * wt; a0.y += v0.y * wt; a0.z += v0.z * wt; a0.w += v0.w * wt;
        a1.x += v1.x * wt; a1.y += v1.y * wt; a1.z += v1.z * wt; a1.w += v1.w * wt;
    }
    float sn = g_dinv[w]; sn *= sn;
    float4 t0 = T[w * 64 + lane], t1 = T[w * 64 + lane + 32];
    const float4* B4 = (const float4*)convBi;
    float4 b0 = B4[lane], b1 = B4[lane + 32];
    a0.x += t0.x * sn + b0.x; a0.y += t0.y * sn + b0.y;
    a0.z += t0.z * sn + b0.z; a0.w += t0.w * sn + b0.w;
    a1.x += t1.x * sn + b1.x; a1.y += t1.y * sn + b1.y;
    a1.z += t1.z * sn + b1.z; a1.w += t1.w * sn + b1.w;
    ((float4*)g_t2)[w * 64 + lane]      = a0;
    ((float4*)g_t2)[w * 64 + lane + 32] = a1;

    int c0 = lane * 4, c1 = 128 + lane * 4;
    atomicAdd(&s_sum[c0+0], a0.x); atomicAdd(&s_sum[c0+1], a0.y);
    atomicAdd(&s_sum[c0+2], a0.z); atomicAdd(&s_sum[c0+3], a0.w);
    atomicAdd(&s_sum[c1+0], a1.x); atomicAdd(&s_sum[c1+1], a1.y);
    atomicAdd(&s_sum[c1+2], a1.z); atomicAdd(&s_sum[c1+3], a1.w);
    atomicAdd(&s_sq[c0+0], a0.x*a0.x); atomicAdd(&s_sq[c0+1], a0.y*a0.y);
    atomicAdd(&s_sq[c0+2], a0.z*a0.z); atomicAdd(&s_sq[c0+3], a0.w*a0.w);
    atomicAdd(&s_sq[c1+0], a1.x*a1.x); atomicAdd(&s_sq[c1+1], a1.y*a1.y);
    atomicAdd(&s_sq[c1+2], a1.z*a1.z); atomicAdd(&s_sq[c1+3], a1.w*a1.w);
    __syncthreads();
    atomicAdd(&g_colsum[tid], s_sum[tid]);
    atomicAdd(&g_colsq[tid],  s_sq[tid]);
}

__global__ void bnprep_k(const float* __restrict__ gamma, const float* __restrict__ beta) {
    int j = threadIdx.x;
    const float invN = 1.f / (float)Nn;
    float m  = g_colsum[j] * invN;
    float v  = g_colsq[j] * invN - m * m;
    float rs = rsqrtf(v + EPSF);
    float sc = gamma[j] * rs;
    g_scale[j] = sc;
    g_shift[j] = beta[j] - m * sc;
    g_colsum[j] = 0.f;
    g_colsq[j]  = 0.f;
}

// BN + ReLU: g_t2 -> g_h (only needed after the last conv layer, for pooling)
__global__ void bnrelu_k() {
    int idx = blockIdx.x * blockDim.x + threadIdx.x;
    if (idx >= Nn * Hh / 4) return;
    int j = (idx & (Hh / 4 - 1)) * 4;
    float4 v = ((const float4*)g_t2)[idx];
    float4 o;
    o.x = fmaxf(v.x * g_scale[j]     + g_shift[j],     0.f);
    o.y = fmaxf(v.y * g_scale[j + 1] + g_shift[j + 1], 0.f);
    o.z = fmaxf(v.z * g_scale[j + 2] + g_shift[j + 2], 0.f);
    o.w = fmaxf(v.w * g_scale[j + 3] + g_shift[j + 3], 0.f);
    ((float4*)g_h)[idx] = o;
}

// ---------------- global mean pool (batch sorted) ----------------
__global__ void pool_k(const int* __restrict__ batch) {
    int j  = threadIdx.x;
    int r0 = blockIdx.x * 80;
    int cur = -1;
    float acc = 0.f;
    for (int r = 0; r < 80; r++) {
        int n = r0 + r;
        if (n >= Nn) break;
        int b = batch[n];
        if (b != cur) {
            if (cur >= 0) atomicAdd(&g_gsum[cur * Hh + j], acc);
            cur = b; acc = 0.f;
        }
        acc += g_h[(size_t)n * Hh + j];
    }
    if (cur >= 0) atomicAdd(&g_gsum[cur * Hh + j], acc);
}

// ---------------- MLP head ----------------
__global__ void mlp1_k(const float* __restrict__ W, const float* __restrict__ b) {
    __shared__ float s[Hh];
    int tid = threadIdx.x;
    int g   = blockIdx.x;
    float inv = 1.f / fmaxf((float)g_gcnt[g], 1.f);
    s[tid] = g_gsum[g * Hh + tid] * inv;
    __syncthreads();
    float sum = b[tid];
#pragma unroll 8
    for (int k = 0; k < Hh; k++) sum += s[k] * W[k * Hh + tid];
    g_m1[g * Hh + tid] = sum;
}

__global__ void mlp2_k(const float* __restrict__ gamma, const float* __restrict__ beta,
                       const float* __restrict__ W, const float* __restrict__ b) {
    __shared__ float s[Hh];
    int tid = threadIdx.x;
    int g   = blockIdx.x;
    float su = 0.f, q = 0.f;
    for (int r = 0; r < GG; r++) { float v = g_m1[r * Hh + tid]; su += v; q += v * v; }
    float m   = su * (1.f / GG);
    float var = q * (1.f / GG) - m * m;
    float sc  = gamma[tid] * rsqrtf(var + EPSF);
    float sh  = beta[tid] - m * sc;
    s[tid] = fmaxf(g_m1[g * Hh + tid] * sc + sh, 0.f);
    __syncthreads();
    float sum = b[tid];
#pragma unroll 8
    for (int k = 0; k < Hh; k++) sum += s[k] * W[k * Hh + tid];
    g_m2[g * Hh + tid] = sum;
}

__global__ void final_k(const float* __restrict__ gamma, const float* __restrict__ beta,
                        const float* __restrict__ W3, const float* __restrict__ b3,
                        float* __restrict__ out) {
    __shared__ float s[Hh];
    int tid = threadIdx.x;
    int g   = blockIdx.x;
    float su = 0.f, q = 0.f;
    for (int r = 0; r < GG; r++) { float v = g_m2[r * Hh + tid]; su += v; q += v * v; }
    float m   = su * (1.f / GG);
    float var = q * (1.f / GG) - m * m;
    float sc  = gamma[tid] * rsqrtf(var + EPSF);
    float sh  = beta[tid] - m * sc;
    s[tid] = g_m2[g * Hh + tid] * sc + sh;
    __syncthreads();
    if (tid < CC) {
        float sum = b3[tid];
        for (int k = 0; k < Hh; k++) sum += s[k] * W3[k * CC + tid];
        out[g * CC + tid] = sum;
    }
}

// ---------------- launch ----------------
extern "C" void kernel_launch(void* const* d_in, const int* in_sizes, int n_in,
                              void* d_out, int out_size) {
    const float* x     = (const float*)d_in[0];
    const int*   ei    = (const int*)  d_in[1];
    const int*   batch = (const int*)  d_in[2];
    const float* encW  = (const float*)d_in[3];
    const float* encB  = (const float*)d_in[4];
    const float* convW = (const float*)d_in[5];
    const float* convB = (const float*)d_in[6];
    const float* bnG   = (const float*)d_in[7];
    const float* bnB   = (const float*)d_in[8];
    const float* fcW1  = (const float*)d_in[9];
    const float* fcB1  = (const float*)d_in[10];
    const float* fcG1  = (const float*)d_in[11];
    const float* fcBe1 = (const float*)d_in[12];
    const float* fcW2  = (const float*)d_in[13];
    const float* fcB2  = (const float*)d_in[14];
    const float* fcG2  = (const float*)d_in[15];
    const float* fcBe2 = (const float*)d_in[16];
    const float* fcW3  = (const float*)d_in[17];
    const float* fcB3  = (const float*)d_in[18];
    const int* srcp = ei;
    const int* dstp = ei + Ee;
    float* out = (float*)d_out;

    dim3 gg(Hh / BN, (Nn + BM - 1) / BM);
    int bnBlocks = (Nn * Hh / 4 + 255) / 256;

    zero_k<<<(GG * Hh + 255) / 256, 256>>>();
    prep_k<<<(KP2TOT * Hh + 255) / 256, 256>>>(encW, convW);
    gemm_k<<<gg, 256>>>(x, encB, 0, 0);                          // enc -> g_h
    gemm_k<<<gg, 256>>>(nullptr, nullptr, 1, (XDIM/2) * Hh);     // conv0 [capture target]

    degree_k<<<(Ee + 255) / 256, 256>>>(dstp, batch);
    scan_k  <<<1, 1024>>>();
    place_k <<<(Ee + 255) / 256, 256>>>(srcp, dstp);

    agg_k   <<<Nn / 8, 256>>>(convB);
    bnprep_k<<<1, 256>>>(bnG, bnB);
    for (int l = 1; l < LL; l++) {
        gemm_k  <<<gg, 256>>>(nullptr, nullptr, 2, (XDIM/2 + l * Hh/2) * Hh);
        agg_k   <<<Nn / 8, 256>>>(convB + l * Hh);
        bnprep_k<<<1, 256>>>(bnG + l * Hh, bnB + l * Hh);
    }
    bnrelu_k<<<bnBlocks, 256>>>();

    pool_k <<<250, 256>>>(batch);
    mlp1_k <<<GG, 256>>>(fcW1, fcB1);
    mlp2_k <<<GG, 256>>>(fcG1, fcBe1, fcW2, fcB2);
    final_k<<<GG, 256>>>(fcG2, fcBe2, fcW3, fcB3, out);
}